// round 2
// baseline (speedup 1.0000x reference)
#include <cuda_runtime.h>
#include <cuda_bf16.h>
#include <cstdint>

#define N_TOK 4096      // B*S = 2*2048
#define HDIM  1024
#define NEXP  16

#define TM 128
#define TN 128
#define TK 32
#define KTILES (HDIM / TK)   // 32
#define SLD 36               // padded smem row stride (floats): bank-conflict-free frag loads
#define STAGE_FLOATS ((TM + TN) * SLD)     // 9216
#define STAGE_BYTES  (STAGE_FLOATS * 4)    // 36864
#define SMEM_TOTAL   (2 * STAGE_BYTES)     // 73728

// ---------------- device scratch (allocation-free rule: __device__ globals) ----------
__device__ int   g_top2_idx[N_TOK * 2];
__device__ float g_top2_w[N_TOK * 2];
__device__ int   g_slot[N_TOK * 2];          // token -> staging row for each of its 2 experts
__device__ int   g_counts[NEXP];
__device__ int   g_offsets[NEXP];
__device__ int   g_fill[NEXP];
__device__ int   g_tok[2 * N_TOK];           // expert-list -> token id
__device__ float g_staging[(size_t)2 * N_TOK * HDIM];   // 32 MB: relu(x@We^T + b) per slot

// ---------------- kernel 1: zero counters ----------------
__global__ void init_kernel() {
    int t = threadIdx.x;
    if (t < NEXP) { g_counts[t] = 0; g_fill[t] = 0; }
}

// ---------------- kernel 2: gate (logits -> softmax -> top2) ----------------
// one block per token, 16 warps, warp w computes logit for expert w
__global__ void gate_kernel(const float* __restrict__ tokens,
                            const float* __restrict__ gate_w) {
    const int n = blockIdx.x;
    const int w = threadIdx.x >> 5;
    const int lane = threadIdx.x & 31;

    const float4* x  = (const float4*)(tokens + (size_t)n * HDIM);
    const float4* gw = (const float4*)(gate_w + (size_t)w * HDIM);
    float s = 0.f;
#pragma unroll
    for (int i = 0; i < HDIM / 4 / 32; i++) {     // 8 iters
        float4 a = x[lane + i * 32];
        float4 b = gw[lane + i * 32];
        s += a.x * b.x + a.y * b.y + a.z * b.z + a.w * b.w;
    }
#pragma unroll
    for (int off = 16; off; off >>= 1) s += __shfl_xor_sync(0xffffffffu, s, off);

    __shared__ float lg[NEXP];
    if (lane == 0) lg[w] = s;
    __syncthreads();

    if (threadIdx.x == 0) {
        float mx = lg[0];
#pragma unroll
        for (int e = 1; e < NEXP; e++) mx = fmaxf(mx, lg[e]);
        float p[NEXP]; float sum = 0.f;
#pragma unroll
        for (int e = 0; e < NEXP; e++) { p[e] = expf(lg[e] - mx); sum += p[e]; }
        float b1 = -1.f, b2 = -1.f; int i1 = 0, i2 = 0;
#pragma unroll
        for (int e = 0; e < NEXP; e++) {
            float v = p[e];
            if (v > b1)      { b2 = b1; i2 = i1; b1 = v; i1 = e; }
            else if (v > b2) { b2 = v;  i2 = e; }
        }
        float inv = 1.f / sum;
        g_top2_idx[n * 2 + 0] = i1;
        g_top2_idx[n * 2 + 1] = i2;
        g_top2_w[n * 2 + 0] = b1 * inv;
        g_top2_w[n * 2 + 1] = b2 * inv;
        atomicAdd(&g_counts[i1], 1);
        atomicAdd(&g_counts[i2], 1);
    }
}

// ---------------- kernel 3: tiny exclusive scan over 16 counts ----------------
__global__ void scan_kernel() {
    if (threadIdx.x == 0) {
        int acc = 0;
#pragma unroll
        for (int e = 0; e < NEXP; e++) { g_offsets[e] = acc; acc += g_counts[e]; }
    }
}

// ---------------- kernel 4: scatter tokens into per-expert lists ----------------
__global__ void scatter_kernel() {
    int n = blockIdx.x * blockDim.x + threadIdx.x;
    if (n >= N_TOK) return;
#pragma unroll
    for (int s = 0; s < 2; s++) {
        int e = g_top2_idx[n * 2 + s];
        int pos = atomicAdd(&g_fill[e], 1);
        int o = g_offsets[e] + pos;
        g_tok[o] = n;
        g_slot[n * 2 + s] = o;
    }
}

// ---------------- kernel 5: grouped expert GEMM (tf32 mma, cp.async pipeline) ----
__device__ __forceinline__ void cpa16(uint32_t dst, const float* src, bool valid) {
    int sz = valid ? 16 : 0;
    asm volatile("cp.async.cg.shared.global [%0], [%1], 16, %2;\n"
                 :: "r"(dst), "l"(src), "r"(sz));
}

__global__ void __launch_bounds__(256)
moe_gemm_kernel(const float* __restrict__ tokens,
                const float* __restrict__ expert_w,
                const float* __restrict__ expert_b) {
    const int e   = blockIdx.z;
    const int cnt = g_counts[e];
    const int m0  = blockIdx.y * TM;
    if (m0 >= cnt) return;
    const int n0   = blockIdx.x * TN;
    const int base = g_offsets[e];

    extern __shared__ float smem[];
    const uint32_t sbase = (uint32_t)__cvta_generic_to_shared(smem);

    const int tid  = threadIdx.x;
    const int lane = tid & 31;
    const int warp = tid >> 5;
    const int g    = lane >> 2;   // group id
    const int c    = lane & 3;    // thread in group
    const int wm0  = (warp & 3) * 32;
    const int wn0  = (warp >> 2) * 64;

    // global load setup: 4 chunks of 16B for A, 4 for B, per thread
    const float* aSrc[4];
    const float* bSrc[4];
    bool aV[4];
    uint32_t offA[4], offB[4];
#pragma unroll
    for (int i = 0; i < 4; i++) {
        int slot = tid + i * 256;
        int r  = slot >> 3;        // 0..127
        int c4 = slot & 7;         // 16B column within 32-float k-slab
        offA[i] = (uint32_t)((r * SLD + c4 * 4) * 4);
        offB[i] = (uint32_t)(TM * SLD * 4) + offA[i];
        int m = m0 + r;
        if (m < cnt) {
            int t = g_tok[base + m];
            aSrc[i] = tokens + (size_t)t * HDIM + c4 * 4;
            aV[i] = true;
        } else {
            aSrc[i] = tokens;   // valid address; zero-filled via src-size 0
            aV[i] = false;
        }
        bSrc[i] = expert_w + (size_t)e * HDIM * HDIM + (size_t)(n0 + r) * HDIM + c4 * 4;
    }

    auto issue_copy = [&](int kt, int stage) {
        uint32_t sb = sbase + (uint32_t)stage * STAGE_BYTES;
        int ko = kt * TK;
#pragma unroll
        for (int i = 0; i < 4; i++) {
            cpa16(sb + offA[i], aSrc[i] + ko, aV[i]);
            cpa16(sb + offB[i], bSrc[i] + ko, true);
        }
    };

    float acc[2][8][4];
#pragma unroll
    for (int mi = 0; mi < 2; mi++)
#pragma unroll
        for (int ni = 0; ni < 8; ni++)
#pragma unroll
            for (int r = 0; r < 4; r++) acc[mi][ni][r] = 0.f;

    issue_copy(0, 0);
    asm volatile("cp.async.commit_group;\n" ::: "memory");

    for (int kt = 0; kt < KTILES; kt++) {
        const int cs = kt & 1;
        if (kt + 1 < KTILES) {
            issue_copy(kt + 1, cs ^ 1);
            asm volatile("cp.async.commit_group;\n" ::: "memory");
            asm volatile("cp.async.wait_group 1;\n" ::: "memory");
        } else {
            asm volatile("cp.async.wait_group 0;\n" ::: "memory");
        }
        __syncthreads();

        const float* sA = smem + cs * STAGE_FLOATS;
        const float* sB = sA + TM * SLD;

#pragma unroll
        for (int ks = 0; ks < 4; ks++) {
            const int k0 = ks * 8;
            uint32_t a0[2], a1[2], a2[2], a3[2];
#pragma unroll
            for (int mi = 0; mi < 2; mi++) {
                const float* ap = sA + (wm0 + mi * 16 + g) * SLD + k0 + c;
                a0[mi] = __float_as_uint(ap[0]);
                a1[mi] = __float_as_uint(ap[8 * SLD]);
                a2[mi] = __float_as_uint(ap[4]);
                a3[mi] = __float_as_uint(ap[8 * SLD + 4]);
            }
#pragma unroll
            for (int ni = 0; ni < 8; ni++) {
                const float* bp = sB + (wn0 + ni * 8 + g) * SLD + k0 + c;
                uint32_t b0 = __float_as_uint(bp[0]);
                uint32_t b1 = __float_as_uint(bp[4]);
#pragma unroll
                for (int mi = 0; mi < 2; mi++) {
                    float* d = acc[mi][ni];
                    asm volatile(
                        "mma.sync.aligned.m16n8k8.row.col.f32.tf32.tf32.f32 "
                        "{%0,%1,%2,%3},{%4,%5,%6,%7},{%8,%9},{%0,%1,%2,%3};\n"
                        : "+f"(d[0]), "+f"(d[1]), "+f"(d[2]), "+f"(d[3])
                        : "r"(a0[mi]), "r"(a1[mi]), "r"(a2[mi]), "r"(a3[mi]),
                          "r"(b0), "r"(b1));
                }
            }
        }
        __syncthreads();
    }

    // epilogue: relu(acc + bias) -> staging rows (no atomics)
    float2 bias2[8];
#pragma unroll
    for (int ni = 0; ni < 8; ni++) {
        int n = n0 + wn0 + ni * 8 + 2 * c;
        bias2[ni] = *(const float2*)(expert_b + (size_t)e * HDIM + n);
    }
#pragma unroll
    for (int mi = 0; mi < 2; mi++) {
#pragma unroll
        for (int half = 0; half < 2; half++) {
            int m = m0 + wm0 + mi * 16 + g + half * 8;
            if (m < cnt) {
                int o = base + m;
                float* orow = g_staging + (size_t)o * HDIM + n0 + wn0 + 2 * c;
#pragma unroll
                for (int ni = 0; ni < 8; ni++) {
                    float v0 = fmaxf(acc[mi][ni][half * 2 + 0] + bias2[ni].x, 0.f);
                    float v1 = fmaxf(acc[mi][ni][half * 2 + 1] + bias2[ni].y, 0.f);
                    *(float2*)(orow + ni * 8) = make_float2(v0, v1);
                }
            }
        }
    }
}

// ---------------- kernel 6: weighted combine of the two expert outputs ----------
__global__ void combine_kernel(float* __restrict__ out) {
    const int n = blockIdx.x;
    const int s0 = g_slot[n * 2 + 0];
    const int s1 = g_slot[n * 2 + 1];
    const float w0 = g_top2_w[n * 2 + 0];
    const float w1 = g_top2_w[n * 2 + 1];
    const float4* a = (const float4*)(g_staging + (size_t)s0 * HDIM);
    const float4* b = (const float4*)(g_staging + (size_t)s1 * HDIM);
    float4* o = (float4*)(out + (size_t)n * HDIM);
    for (int i = threadIdx.x; i < HDIM / 4; i += blockDim.x) {
        float4 x = a[i], y = b[i];
        o[i] = make_float4(w0 * x.x + w1 * y.x,
                           w0 * x.y + w1 * y.y,
                           w0 * x.z + w1 * y.z,
                           w0 * x.w + w1 * y.w);
    }
}

// ---------------- launch ----------------
extern "C" void kernel_launch(void* const* d_in, const int* in_sizes, int n_in,
                              void* d_out, int out_size) {
    const float* tokens   = (const float*)d_in[0];
    const float* gate_w   = (const float*)d_in[1];
    const float* expert_w = (const float*)d_in[2];
    const float* expert_b = (const float*)d_in[3];
    float* out = (float*)d_out;

    cudaFuncSetAttribute(moe_gemm_kernel,
                         cudaFuncAttributeMaxDynamicSharedMemorySize, SMEM_TOTAL);

    init_kernel<<<1, 32>>>();
    gate_kernel<<<N_TOK, 512>>>(tokens, gate_w);
    scan_kernel<<<1, 32>>>();
    scatter_kernel<<<N_TOK / 256, 256>>>();
    moe_gemm_kernel<<<dim3(HDIM / TN, N_TOK / TM, NEXP), 256, SMEM_TOTAL>>>(
        tokens, expert_w, expert_b);
    combine_kernel<<<N_TOK, 256>>>(out);
}